// round 5
// baseline (speedup 1.0000x reference)
#include <cuda_runtime.h>
#include <cstdint>

// Problem constants
#define NPTS   32768            // 32 * 32 * 32 points
#define DIM    64               // embedding dim
#define NE     1024             // codebook size
#define HW     1024             // 32*32 spatial
#define BHW    65536            // 64 channels * 1024 hw (per-batch stride in z)
#define PTSB   64               // points per block

// Output layout (flat concat of reference return tuple, float32):
// loss[1], z_q[2097152], perplexity[1], min_encodings[33554432], indices[32768]
#define OFF_LOSS 0ULL
#define OFF_ZQ   1ULL
#define OFF_PERP 2097153ULL
#define OFF_ENC  2097154ULL
#define OFF_IDX  35651586ULL

__device__ float        d_esq[NE];
__device__ float        d_est[DIM * NE];   // transposed codebook [k][c]
__device__ unsigned int d_count[NE];
__device__ float        d_loss;

// ---------------------------------------------------------------- helpers
struct __align__(16) ull2 { unsigned long long a, b; };

static __device__ __forceinline__ unsigned long long pk2(float v) {
    unsigned long long r;
    asm("mov.b64 %0, {%1,%2};" : "=l"(r) : "f"(v), "f"(v));
    return r;
}
static __device__ __forceinline__ void ffma2(unsigned long long& d,
                                             unsigned long long a,
                                             unsigned long long b) {
    // packed 2-wide fp32 FMA (Blackwell f32x2 pipe)
    asm("fma.rn.f32x2 %0, %1, %2, %0;" : "+l"(d) : "l"(a), "l"(b));
}
static __device__ __forceinline__ float2 upk(unsigned long long v) {
    float2 f;
    asm("mov.b64 {%0,%1}, %2;" : "=f"(f.x), "=f"(f.y) : "l"(v));
    return f;
}
// monotonic float->uint mapping for ordered compare
static __device__ __forceinline__ unsigned int ordf(float x) {
    unsigned int b = __float_as_uint(x);
    return b ^ (unsigned int)(((int)b >> 31) | 0x80000000);
}
// shuffled column for point p inside the z tile (conflict-free LDS.128 quads)
static __device__ __forceinline__ int zcol(int p) {
    return ((p >> 2) & 1) * 32 + (p >> 3) * 4 + (p & 3);
}

// ---------------------------------------------------------------- prep
// 16 blocks x 128 threads; block handles 64 codes. Verified 5.1-5.4us.
__global__ void prep_kernel(const float* __restrict__ emb) {
    __shared__ float sb[64][DIM + 1];        // padded: conflict-free row sums
    const int tid = threadIdx.x;
    const int c0  = blockIdx.x * 64;

    const float4* src = (const float4*)(emb + (size_t)c0 * DIM);
    #pragma unroll
    for (int i = 0; i < 8; ++i) {
        int f  = i * 128 + tid;
        int c  = f >> 4;
        int k4 = f & 15;
        float4 v = src[f];
        sb[c][k4 * 4 + 0] = v.x;
        sb[c][k4 * 4 + 1] = v.y;
        sb[c][k4 * 4 + 2] = v.z;
        sb[c][k4 * 4 + 3] = v.w;
    }
    __syncthreads();

    if (tid < 64) {
        const int c = c0 + tid;
        float s = 0.f;
        #pragma unroll
        for (int k = 0; k < DIM; ++k) {
            float v = sb[tid][k];
            s = __fadd_rn(s, __fmul_rn(v, v));
            d_est[k * NE + c] = v;
        }
        d_esq[c]   = s;
        d_count[c] = 0u;
        if (c == 0) d_loss = 0.f;
    }
}

// ---------------------------------------------------------------- main fused kernel
// block: 128 threads = 8 point-threads (pt_t, 8 pts each) x 16 code-threads (ct, 8 codes)
// block tile: 64 points x 128 codes per chunk (8 chunks -> 1024 codes)
// thread tile: 8 points x 8 codes; f32x2 lanes = code pairs, z dup'd in regs
__global__ void __launch_bounds__(128, 3)
vq_main_kernel(const float* __restrict__ z, const float* __restrict__ emb,
               float* __restrict__ out)
{
    __shared__ __align__(16) float zst[DIM][PTSB];   // shuffled z tile, 16 KB
    __shared__ __align__(16) float es[DIM][128];     // [k][c] chunk, 32 KB
    __shared__ float zsq_s[PTSB];
    // red overlays es (used only after the last chunk's FMAs)
    unsigned long long (*red)[PTSB] = (unsigned long long (*)[PTSB])&es[0][0];

    const int tid  = threadIdx.x;
    const int pt_t = tid & 7;     // 0..7  (point group of 8)
    const int ct   = tid >> 3;    // 0..15 (code group of 8)  -- same es pattern as R2
    const int pt0  = blockIdx.x * PTSB;
    const int b    = pt0 >> 10;
    const int hw0  = pt0 & 1023;
    const float* zb = z + (size_t)b * BHW + hw0;

    // load z tile (coalesced gmem), store shuffled columns
    #pragma unroll
    for (int i = 0; i < 32; ++i) {
        int f = i * 128 + tid;
        int k = f >> 6, p = f & 63;
        zst[k][zcol(p)] = zb[(size_t)k * HW + p];
    }

    // fused zero-fill of this block's one-hot rows (65536 floats, base%4==2)
    {
        float* encb = out + OFF_ENC + (size_t)pt0 * NE;
        if (tid == 0) {
            encb[0] = 0.f; encb[1] = 0.f;
            encb[65534] = 0.f; encb[65535] = 0.f;
        }
        float4* e4 = (float4*)(encb + 2);                 // 16B aligned
        #pragma unroll
        for (int i = 0; i < 128; ++i) {
            int j = tid + 128 * i;
            if (j < 16383) e4[j] = make_float4(0.f, 0.f, 0.f, 0.f);
        }
    }
    __syncthreads();

    // per-point ||z||^2, sequential fp32 rn (matches reference rounding)
    if (tid < PTSB) {
        const int col = zcol(tid);
        float s = 0.f;
        #pragma unroll
        for (int k = 0; k < DIM; ++k) {
            float v = zst[k][col];
            s = __fadd_rn(s, __fmul_rn(v, v));
        }
        zsq_s[tid] = s;
    }
    __syncthreads();

    // cache this thread's 8 zsq values (zsq_s lives in smem only until red overlay? no:
    // zsq_s is its own array, safe) -- read on the fly below.

    unsigned long long best[8];
    #pragma unroll
    for (int p = 0; p < 8; ++p) best[p] = 0xFFFFFFFFFFFFFFFFULL;

    for (int chunk = 0; chunk < 8; ++chunk) {
        __syncthreads();   // previous chunk's es consumers done
        // load transposed es chunk [64][128] from d_est, coalesced float4
        #pragma unroll
        for (int i = 0; i < 16; ++i) {
            int f  = i * 128 + tid;        // 0..2047 float4s
            int k  = f >> 5;               // 32 float4 per row
            int c4 = f & 31;
            *(float4*)&es[k][c4 * 4] =
                *(const float4*)&d_est[(size_t)k * NE + chunk * 128 + c4 * 4];
        }
        __syncthreads();

        unsigned long long acc[8][4];      // [point][code-pair]
        #pragma unroll
        for (int p = 0; p < 8; ++p)
            #pragma unroll
            for (int j = 0; j < 4; ++j) acc[p][j] = 0ULL;

        #pragma unroll 4
        for (int k = 0; k < DIM; ++k) {
            ull2 eA = *(const ull2*)&es[k][ct * 8];       // code pairs 0,1
            ull2 eB = *(const ull2*)&es[k][ct * 8 + 4];   // code pairs 2,3
            // points 0..3 of this thread's group (conflict-free 16B-stride quad)
            float4 za = *(const float4*)&zst[k][pt_t * 4];
            {
                unsigned long long d0 = pk2(za.x), d1 = pk2(za.y);
                unsigned long long d2 = pk2(za.z), d3 = pk2(za.w);
                ffma2(acc[0][0], d0, eA.a); ffma2(acc[0][1], d0, eA.b);
                ffma2(acc[0][2], d0, eB.a); ffma2(acc[0][3], d0, eB.b);
                ffma2(acc[1][0], d1, eA.a); ffma2(acc[1][1], d1, eA.b);
                ffma2(acc[1][2], d1, eB.a); ffma2(acc[1][3], d1, eB.b);
                ffma2(acc[2][0], d2, eA.a); ffma2(acc[2][1], d2, eA.b);
                ffma2(acc[2][2], d2, eB.a); ffma2(acc[2][3], d2, eB.b);
                ffma2(acc[3][0], d3, eA.a); ffma2(acc[3][1], d3, eA.b);
                ffma2(acc[3][2], d3, eB.a); ffma2(acc[3][3], d3, eB.b);
            }
            // points 4..7
            float4 zc = *(const float4*)&zst[k][32 + pt_t * 4];
            {
                unsigned long long d0 = pk2(zc.x), d1 = pk2(zc.y);
                unsigned long long d2 = pk2(zc.z), d3 = pk2(zc.w);
                ffma2(acc[4][0], d0, eA.a); ffma2(acc[4][1], d0, eA.b);
                ffma2(acc[4][2], d0, eB.a); ffma2(acc[4][3], d0, eB.b);
                ffma2(acc[5][0], d1, eA.a); ffma2(acc[5][1], d1, eA.b);
                ffma2(acc[5][2], d1, eB.a); ffma2(acc[5][3], d1, eB.b);
                ffma2(acc[6][0], d2, eA.a); ffma2(acc[6][1], d2, eA.b);
                ffma2(acc[6][2], d2, eB.a); ffma2(acc[6][3], d2, eB.b);
                ffma2(acc[7][0], d3, eA.a); ffma2(acc[7][1], d3, eA.b);
                ffma2(acc[7][2], d3, eB.a); ffma2(acc[7][3], d3, eB.b);
            }
        }

        // distances + running argmin (u64 key -> first-index tie-break)
        const int cbase = chunk * 128 + ct * 8;
        #pragma unroll
        for (int j = 0; j < 4; ++j) {
            float esq0 = __ldg(&d_esq[cbase + 2 * j]);
            float esq1 = __ldg(&d_esq[cbase + 2 * j + 1]);
            #pragma unroll
            for (int p = 0; p < 8; ++p) {
                float zq2 = zsq_s[pt_t * 8 + p];
                float2 dot = upk(acc[p][j]);
                {
                    float d = __fadd_rn(__fadd_rn(zq2, esq0), -2.0f * dot.x);
                    unsigned long long k64 =
                        ((unsigned long long)ordf(d) << 32) | (unsigned)(cbase + 2 * j);
                    if (k64 < best[p]) best[p] = k64;
                }
                {
                    float d = __fadd_rn(__fadd_rn(zq2, esq1), -2.0f * dot.y);
                    unsigned long long k64 =
                        ((unsigned long long)ordf(d) << 32) | (unsigned)(cbase + 2 * j + 1);
                    if (k64 < best[p]) best[p] = k64;
                }
            }
        }
    }

    // cross-thread argmin reduction per point (red overlays es; synced above)
    __syncthreads();
    #pragma unroll
    for (int p = 0; p < 8; ++p) red[ct][pt_t * 8 + p] = best[p];
    __syncthreads();

    if (tid < PTSB) {
        unsigned long long bk = red[0][tid];
        #pragma unroll
        for (int t = 1; t < 16; ++t) {
            unsigned long long v = red[t][tid];
            if (v < bk) bk = v;
        }
        int idx = (int)(unsigned int)bk;
        int n   = pt0 + tid;

        out[OFF_IDX + n] = (float)idx;
        atomicAdd(&d_count[idx], 1u);
        out[OFF_ENC + (unsigned long long)n * NE + (unsigned)idx] = 1.0f;

        // z_q gather + loss partial (straight-through: z_q_out == z_q in value)
        float errsum = 0.f;
        const int col = zcol(tid);
        const float* er = emb + (size_t)idx * DIM;
        float* zq = out + OFF_ZQ + (size_t)b * BHW + hw0 + tid;
        #pragma unroll
        for (int c = 0; c < DIM; ++c) {
            float e  = __ldg(er + c);
            float zv = zst[c][col];
            float df = e - zv;
            errsum   = fmaf(df, df, errsum);
            zq[(size_t)c * HW] = e;
        }
        // reduce within each of the two active warps
        #pragma unroll
        for (int o = 16; o > 0; o >>= 1)
            errsum += __shfl_down_sync(0xFFFFFFFFu, errsum, o);
        if ((tid & 31) == 0) atomicAdd(&d_loss, errsum);
    }
}

// ---------------------------------------------------------------- finalize scalars
__global__ void finalize_kernel(float* __restrict__ out) {
    __shared__ float warp_s[32];
    int t = threadIdx.x;  // 1024 threads
    float em = (float)d_count[t] * (1.0f / 32768.0f);
    float v  = em * logf(em + 1e-10f);
    #pragma unroll
    for (int o = 16; o > 0; o >>= 1) v += __shfl_down_sync(0xFFFFFFFFu, v, o);
    if ((t & 31) == 0) warp_s[t >> 5] = v;
    __syncthreads();
    if (t < 32) {
        float w = warp_s[t];
        #pragma unroll
        for (int o = 16; o > 0; o >>= 1) w += __shfl_down_sync(0xFFFFFFFFu, w, o);
        if (t == 0) {
            out[OFF_PERP] = expf(-w);
            out[OFF_LOSS] = 1.25f * d_loss * (1.0f / 2097152.0f);
        }
    }
}

// ---------------------------------------------------------------- launch
extern "C" void kernel_launch(void* const* d_in, const int* in_sizes, int n_in,
                              void* d_out, int out_size) {
    const float* z   = (const float*)d_in[0];
    const float* emb = (const float*)d_in[1];
    float*       out = (float*)d_out;

    prep_kernel<<<16, 128>>>(emb);
    vq_main_kernel<<<NPTS / PTSB, 128>>>(z, emb, out);
    finalize_kernel<<<1, 1024>>>(out);
}

// round 6
// speedup vs baseline: 1.0578x; 1.0578x over previous
#include <cuda_runtime.h>
#include <cstdint>

// Problem constants
#define NPTS   32768            // 32 * 32 * 32 points
#define DIM    64               // embedding dim
#define NE     1024             // codebook size
#define HW     1024             // 32*32 spatial
#define BHW    65536            // 64 channels * 1024 hw (per-batch stride in z)
#define PTSB   64               // points per block

// Output layout (flat concat of reference return tuple, float32):
// loss[1], z_q[2097152], perplexity[1], min_encodings[33554432], indices[32768]
#define OFF_LOSS 0ULL
#define OFF_ZQ   1ULL
#define OFF_PERP 2097153ULL
#define OFF_ENC  2097154ULL
#define OFF_IDX  35651586ULL

__device__ float        d_esq[NE];
__device__ float        d_est[DIM * NE];   // transposed codebook [k][c]
__device__ unsigned int d_count[NE];
__device__ float        d_loss;

// ---------------------------------------------------------------- helpers
struct __align__(16) ull2 { unsigned long long a, b; };

static __device__ __forceinline__ unsigned long long pk2(float v) {
    unsigned long long r;
    asm("mov.b64 %0, {%1,%2};" : "=l"(r) : "f"(v), "f"(v));
    return r;
}
static __device__ __forceinline__ void ffma2(unsigned long long& d,
                                             unsigned long long a,
                                             unsigned long long b) {
    // packed 2-wide fp32 FMA (Blackwell f32x2 pipe)
    asm("fma.rn.f32x2 %0, %1, %2, %0;" : "+l"(d) : "l"(a), "l"(b));
}
static __device__ __forceinline__ float2 upk(unsigned long long v) {
    float2 f;
    asm("mov.b64 {%0,%1}, %2;" : "=f"(f.x), "=f"(f.y) : "l"(v));
    return f;
}
// monotonic float->uint mapping for ordered compare
static __device__ __forceinline__ unsigned int ordf(float x) {
    unsigned int b = __float_as_uint(x);
    return b ^ (unsigned int)(((int)b >> 31) | 0x80000000);
}

// ---------------------------------------------------------------- prep
// 16 blocks x 128 threads; block handles 64 codes. Verified 5.1-5.4us.
__global__ void prep_kernel(const float* __restrict__ emb) {
    __shared__ float sb[64][DIM + 1];        // padded: conflict-free row sums
    const int tid = threadIdx.x;
    const int c0  = blockIdx.x * 64;

    const float4* src = (const float4*)(emb + (size_t)c0 * DIM);
    #pragma unroll
    for (int i = 0; i < 8; ++i) {
        int f  = i * 128 + tid;
        int c  = f >> 4;
        int k4 = f & 15;
        float4 v = src[f];
        sb[c][k4 * 4 + 0] = v.x;
        sb[c][k4 * 4 + 1] = v.y;
        sb[c][k4 * 4 + 2] = v.z;
        sb[c][k4 * 4 + 3] = v.w;
    }
    __syncthreads();

    if (tid < 64) {
        const int c = c0 + tid;
        float s = 0.f;
        #pragma unroll
        for (int k = 0; k < DIM; ++k) {
            float v = sb[tid][k];
            s = __fadd_rn(s, __fmul_rn(v, v));
            d_est[k * NE + c] = v;
        }
        d_esq[c]   = s;
        d_count[c] = 0u;
        if (c == 0) d_loss = 0.f;
    }
}

// ---------------------------------------------------------------- main fused kernel
// block: 128 threads = 8 pt-groups (pt_t) x 16 code-groups (ct)
// block tile: 64 points x 128 codes per chunk (8 chunks -> 1024 codes)
// thread tile: 8 points (4 NATURAL f32x2 pairs from smem) x 8 codes
//   -> acc[4][8] u64 = 64 regs, 32 ffma2 per k, no z pack MOVs
__global__ void __launch_bounds__(128, 3)
vq_main_kernel(const float* __restrict__ z, const float* __restrict__ emb,
               float* __restrict__ out)
{
    __shared__ __align__(16) float zs[DIM][PTSB];    // natural [k][pt], 16 KB
    __shared__ __align__(16) float es[DIM][128];     // [k][c] chunk, 32 KB
    __shared__ float zsq_s[PTSB];
    // red overlays es (used only after the last chunk's FMAs)
    unsigned long long (*red)[PTSB] = (unsigned long long (*)[PTSB])&es[0][0];

    const int tid  = threadIdx.x;
    const int pt_t = tid & 7;     // 0..7  point group
    const int ct   = tid >> 3;    // 0..15 code group (8 codes each)
    const int pt0  = blockIdx.x * PTSB;
    const int b    = pt0 >> 10;
    const int hw0  = pt0 & 1023;
    const float* zb = z + (size_t)b * BHW + hw0;

    // load z tile (coalesced), natural layout
    #pragma unroll
    for (int i = 0; i < 32; ++i) {
        int f = i * 128 + tid;
        int k = f >> 6, p = f & 63;
        zs[k][p] = zb[(size_t)k * HW + p];
    }

    // fused zero-fill of this block's one-hot rows (65536 floats, base%4==2)
    {
        float* encb = out + OFF_ENC + (size_t)pt0 * NE;
        if (tid == 0) {
            encb[0] = 0.f; encb[1] = 0.f;
            encb[65534] = 0.f; encb[65535] = 0.f;
        }
        float4* e4 = (float4*)(encb + 2);                 // 16B aligned
        #pragma unroll
        for (int i = 0; i < 128; ++i) {
            int j = tid + 128 * i;
            if (j < 16383) e4[j] = make_float4(0.f, 0.f, 0.f, 0.f);
        }
    }
    __syncthreads();

    // per-point ||z||^2, sequential fp32 rn (matches reference rounding)
    if (tid < PTSB) {
        float s = 0.f;
        #pragma unroll
        for (int k = 0; k < DIM; ++k) {
            float v = zs[k][tid];
            s = __fadd_rn(s, __fmul_rn(v, v));
        }
        zsq_s[tid] = s;
    }

    unsigned long long best[8];   // indexed by local point lp = pp*2 + (0|1)
    #pragma unroll
    for (int p = 0; p < 8; ++p) best[p] = 0xFFFFFFFFFFFFFFFFULL;

    for (int chunk = 0; chunk < 8; ++chunk) {
        __syncthreads();   // previous chunk's es consumers done (covers zsq_s too)
        // load transposed es chunk [64][128] from d_est, coalesced float4
        #pragma unroll
        for (int i = 0; i < 16; ++i) {
            int f  = i * 128 + tid;        // 0..2047 float4s
            int k  = f >> 5;               // 32 float4 per row
            int c4 = f & 31;
            *(float4*)&es[k][c4 * 4] =
                *(const float4*)&d_est[(size_t)k * NE + chunk * 128 + c4 * 4];
        }
        __syncthreads();

        unsigned long long acc[4][8];      // [point-pair][code]
        #pragma unroll
        for (int pp = 0; pp < 4; ++pp)
            #pragma unroll
            for (int j = 0; j < 8; ++j) acc[pp][j] = 0ULL;

        #pragma unroll 4
        for (int k = 0; k < DIM; ++k) {
            // 4 natural point-pairs: points pt_t*4..+3 and 32+pt_t*4..+3
            ull2 zA = *(const ull2*)&zs[k][pt_t * 4];        // pairs 0,1
            ull2 zB = *(const ull2*)&zs[k][32 + pt_t * 4];   // pairs 2,3
            const float* ek = &es[k][ct * 8];
            #pragma unroll
            for (int j = 0; j < 8; ++j) {
                unsigned long long ed = pk2(ek[j]);          // {e,e}
                ffma2(acc[0][j], zA.a, ed);
                ffma2(acc[1][j], zA.b, ed);
                ffma2(acc[2][j], zB.a, ed);
                ffma2(acc[3][j], zB.b, ed);
            }
        }

        // distances + running argmin (u64 key -> first-index tie-break)
        const int cbase = chunk * 128 + ct * 8;
        #pragma unroll
        for (int j = 0; j < 8; ++j) {
            float esq = __ldg(&d_esq[cbase + j]);
            unsigned code = (unsigned)(cbase + j);
            #pragma unroll
            for (int pp = 0; pp < 4; ++pp) {
                int pbase = (pp >> 1) * 32 + pt_t * 4 + (pp & 1) * 2;
                float2 dot = upk(acc[pp][j]);
                {
                    float zq2 = zsq_s[pbase];
                    float d = __fadd_rn(__fadd_rn(zq2, esq), -2.0f * dot.x);
                    unsigned long long k64 =
                        ((unsigned long long)ordf(d) << 32) | code;
                    if (k64 < best[pp * 2]) best[pp * 2] = k64;
                }
                {
                    float zq2 = zsq_s[pbase + 1];
                    float d = __fadd_rn(__fadd_rn(zq2, esq), -2.0f * dot.y);
                    unsigned long long k64 =
                        ((unsigned long long)ordf(d) << 32) | code;
                    if (k64 < best[pp * 2 + 1]) best[pp * 2 + 1] = k64;
                }
            }
        }
    }

    // cross-thread argmin reduction per point (red overlays es; synced above)
    __syncthreads();
    #pragma unroll
    for (int pp = 0; pp < 4; ++pp) {
        int pbase = (pp >> 1) * 32 + pt_t * 4 + (pp & 1) * 2;
        red[ct][pbase]     = best[pp * 2];
        red[ct][pbase + 1] = best[pp * 2 + 1];
    }
    __syncthreads();

    if (tid < PTSB) {
        unsigned long long bk = red[0][tid];
        #pragma unroll
        for (int t = 1; t < 16; ++t) {
            unsigned long long v = red[t][tid];
            if (v < bk) bk = v;
        }
        int idx = (int)(unsigned int)bk;
        int n   = pt0 + tid;

        out[OFF_IDX + n] = (float)idx;
        atomicAdd(&d_count[idx], 1u);
        out[OFF_ENC + (unsigned long long)n * NE + (unsigned)idx] = 1.0f;

        // z_q gather + loss partial (straight-through: z_q_out == z_q in value)
        float errsum = 0.f;
        const float* er = emb + (size_t)idx * DIM;
        float* zq = out + OFF_ZQ + (size_t)b * BHW + hw0 + tid;
        #pragma unroll
        for (int c = 0; c < DIM; ++c) {
            float e  = __ldg(er + c);
            float zv = zs[c][tid];
            float df = e - zv;
            errsum   = fmaf(df, df, errsum);
            zq[(size_t)c * HW] = e;
        }
        // reduce within each of the two active warps
        #pragma unroll
        for (int o = 16; o > 0; o >>= 1)
            errsum += __shfl_down_sync(0xFFFFFFFFu, errsum, o);
        if ((tid & 31) == 0) atomicAdd(&d_loss, errsum);
    }
}

// ---------------------------------------------------------------- finalize scalars
__global__ void finalize_kernel(float* __restrict__ out) {
    __shared__ float warp_s[32];
    int t = threadIdx.x;  // 1024 threads
    float em = (float)d_count[t] * (1.0f / 32768.0f);
    float v  = em * logf(em + 1e-10f);
    #pragma unroll
    for (int o = 16; o > 0; o >>= 1) v += __shfl_down_sync(0xFFFFFFFFu, v, o);
    if ((t & 31) == 0) warp_s[t >> 5] = v;
    __syncthreads();
    if (t < 32) {
        float w = warp_s[t];
        #pragma unroll
        for (int o = 16; o > 0; o >>= 1) w += __shfl_down_sync(0xFFFFFFFFu, w, o);
        if (t == 0) {
            out[OFF_PERP] = expf(-w);
            out[OFF_LOSS] = 1.25f * d_loss * (1.0f / 2097152.0f);
        }
    }
}

// ---------------------------------------------------------------- launch
extern "C" void kernel_launch(void* const* d_in, const int* in_sizes, int n_in,
                              void* d_out, int out_size) {
    const float* z   = (const float*)d_in[0];
    const float* emb = (const float*)d_in[1];
    float*       out = (float*)d_out;

    prep_kernel<<<16, 128>>>(emb);
    vq_main_kernel<<<NPTS / PTSB, 128>>>(z, emb, out);
    finalize_kernel<<<1, 1024>>>(out);
}

// round 7
// speedup vs baseline: 1.1292x; 1.0675x over previous
#include <cuda_runtime.h>
#include <cstdint>

// Problem constants
#define NPTS   32768            // 32 * 32 * 32 points
#define DIM    64               // embedding dim
#define NE     1024             // codebook size
#define HW     1024             // 32*32 spatial
#define BHW    65536            // 64 channels * 1024 hw (per-batch stride in z)
#define PTSB   64               // points per block
#define HCH    64               // codes per half-chunk
#define NH     16               // number of half-chunks

// Output layout (flat concat of reference return tuple, float32):
// loss[1], z_q[2097152], perplexity[1], min_encodings[33554432], indices[32768]
#define OFF_LOSS 0ULL
#define OFF_ZQ   1ULL
#define OFF_PERP 2097153ULL
#define OFF_ENC  2097154ULL
#define OFF_IDX  35651586ULL

__device__ float        d_esq[NE];
__device__ float        d_est[DIM * NE];   // transposed codebook [k][c]
__device__ unsigned int d_count[NE];
__device__ float        d_loss;

// ---------------------------------------------------------------- helpers
static __device__ __forceinline__ unsigned long long pk2(float v) {
    unsigned long long r;
    asm("mov.b64 %0, {%1,%2};" : "=l"(r) : "f"(v), "f"(v));
    return r;
}
static __device__ __forceinline__ void ffma2(unsigned long long& d,
                                             unsigned long long a,
                                             unsigned long long b) {
    asm("fma.rn.f32x2 %0, %1, %2, %0;" : "+l"(d) : "l"(a), "l"(b));
}
static __device__ __forceinline__ float2 upk(unsigned long long v) {
    float2 f;
    asm("mov.b64 {%0,%1}, %2;" : "=f"(f.x), "=f"(f.y) : "l"(v));
    return f;
}
static __device__ __forceinline__ unsigned int ordf(float x) {
    unsigned int b = __float_as_uint(x);
    return b ^ (unsigned int)(((int)b >> 31) | 0x80000000);
}
static __device__ __forceinline__ void cpasync16(unsigned int dst_smem,
                                                 const void* src) {
    asm volatile("cp.async.ca.shared.global [%0], [%1], 16;"
                 :: "r"(dst_smem), "l"(src));
}
#define CP_COMMIT() asm volatile("cp.async.commit_group;" ::: "memory")
#define CP_WAIT0()  asm volatile("cp.async.wait_group 0;" ::: "memory")

// ---------------------------------------------------------------- prep
// 16 blocks x 128 threads; block handles 64 codes. Verified ~5.1us.
__global__ void prep_kernel(const float* __restrict__ emb) {
    __shared__ float sb[64][DIM + 1];
    const int tid = threadIdx.x;
    const int c0  = blockIdx.x * 64;

    const float4* src = (const float4*)(emb + (size_t)c0 * DIM);
    #pragma unroll
    for (int i = 0; i < 8; ++i) {
        int f  = i * 128 + tid;
        int c  = f >> 4;
        int k4 = f & 15;
        float4 v = src[f];
        sb[c][k4 * 4 + 0] = v.x;
        sb[c][k4 * 4 + 1] = v.y;
        sb[c][k4 * 4 + 2] = v.z;
        sb[c][k4 * 4 + 3] = v.w;
    }
    __syncthreads();

    if (tid < 64) {
        const int c = c0 + tid;
        float s = 0.f;
        #pragma unroll
        for (int k = 0; k < DIM; ++k) {
            float v = sb[tid][k];
            s = __fadd_rn(s, __fmul_rn(v, v));
            d_est[k * NE + c] = v;
        }
        d_esq[c]   = s;
        d_count[c] = 0u;
        if (c == 0) d_loss = 0.f;
    }
}

// ---------------------------------------------------------------- main fused kernel
// block: 128 threads = 16 pt-groups (pt_t, 4 pts) x 8 code-groups (cg, 8 codes)
// block tile: 64 points x 64 codes per half-chunk (16 half-chunks -> 1024 codes)
// thread tile: 4 points x 8 codes (4 f32x2 code-pairs)  -> acc[4][4] u64 = 64 regs
// es double-buffered via cp.async; one-hot zero-fill interleaved per iteration.
__global__ void __launch_bounds__(128, 4)
vq_main_kernel(const float* __restrict__ z, const float* __restrict__ emb,
               float* __restrict__ out)
{
    __shared__ __align__(16) float zs[DIM][PTSB];      // natural [k][pt], 16 KB
    __shared__ __align__(16) float es[2][DIM][HCH];    // double buf, 2x16 KB
    __shared__ float zsq_s[PTSB];
    __shared__ unsigned long long red[8][PTSB];        // 4 KB

    const int tid  = threadIdx.x;
    const int pt_t = tid & 15;    // 0..15 point group (4 pts each)
    const int cg   = tid >> 4;    // 0..7  code group  (8 codes each)
    const int pt0  = blockIdx.x * PTSB;
    const int b    = pt0 >> 10;
    const int hw0  = pt0 & 1023;
    const float* zb = z + (size_t)b * BHW + hw0;

    // issue es half-chunk 0 fetch immediately (overlaps zs load)
    // thread covers 8 x 16B: f = i*128+tid, k = f>>4, c16 = f&15
    {
        unsigned int dst0 = (unsigned int)__cvta_generic_to_shared(&es[0][0][0]);
        #pragma unroll
        for (int i = 0; i < 8; ++i) {
            int f = i * 128 + tid;
            int k = f >> 4, c16 = f & 15;
            cpasync16(dst0 + (unsigned)(k * HCH + c16 * 4) * 4u,
                      &d_est[(size_t)k * NE + 0 * HCH + c16 * 4]);
        }
        CP_COMMIT();
    }

    // load z tile (coalesced), natural layout
    #pragma unroll
    for (int i = 0; i < 32; ++i) {
        int f = i * 128 + tid;
        int k = f >> 6, p = f & 63;
        zs[k][p] = zb[(size_t)k * HW + p];
    }

    // one-hot region head/tail scalars (base%4==2); float4 body interleaved below
    float* encb = out + OFF_ENC + (size_t)pt0 * NE;    // 65536 floats
    float4* e4  = (float4*)(encb + 2);                 // 16383 float4s
    if (tid == 0) {
        encb[0] = 0.f; encb[1] = 0.f;
        encb[65534] = 0.f; encb[65535] = 0.f;
    }
    __syncthreads();

    // per-point ||z||^2, sequential fp32 rn (matches reference rounding)
    if (tid < PTSB) {
        float s = 0.f;
        #pragma unroll
        for (int k = 0; k < DIM; ++k) {
            float v = zs[k][tid];
            s = __fadd_rn(s, __fmul_rn(v, v));
        }
        zsq_s[tid] = s;
    }

    unsigned long long best[4];
    #pragma unroll
    for (int p = 0; p < 4; ++p) best[p] = 0xFFFFFFFFFFFFFFFFULL;

    for (int h = 0; h < NH; ++h) {
        const int buf = h & 1;
        CP_WAIT0();            // this thread's half-chunk h slice landed
        __syncthreads();       // all slices visible; all done computing h-1

        // prefetch half-chunk h+1 into the other buffer (overlaps compute)
        if (h + 1 < NH) {
            unsigned int dstn = (unsigned int)__cvta_generic_to_shared(
                &es[buf ^ 1][0][0]);
            #pragma unroll
            for (int i = 0; i < 8; ++i) {
                int f = i * 128 + tid;
                int k = f >> 4, c16 = f & 15;
                cpasync16(dstn + (unsigned)(k * HCH + c16 * 4) * 4u,
                          &d_est[(size_t)k * NE + (h + 1) * HCH + c16 * 4]);
            }
        }
        CP_COMMIT();           // commit (possibly empty) group each iter

        // interleaved one-hot zero-fill slice (drains on HBM under the FMAs)
        #pragma unroll
        for (int i = 0; i < 8; ++i) {
            int j = h * 1024 + i * 128 + tid;
            if (j < 16383) e4[j] = make_float4(0.f, 0.f, 0.f, 0.f);
        }

        unsigned long long acc[4][4];      // [point][code-pair]
        #pragma unroll
        for (int p = 0; p < 4; ++p)
            #pragma unroll
            for (int j = 0; j < 4; ++j) acc[p][j] = 0ULL;

        #pragma unroll 8
        for (int k = 0; k < DIM; ++k) {
            float4 zv = *(const float4*)&zs[k][pt_t * 4];
            unsigned long long z0 = pk2(zv.x), z1 = pk2(zv.y);
            unsigned long long z2 = pk2(zv.z), z3 = pk2(zv.w);
            const unsigned long long* ep =
                (const unsigned long long*)&es[buf][k][cg * 8];
            #pragma unroll
            for (int j = 0; j < 4; ++j) {
                unsigned long long e2 = ep[j];     // codes (2j, 2j+1)
                ffma2(acc[0][j], z0, e2);
                ffma2(acc[1][j], z1, e2);
                ffma2(acc[2][j], z2, e2);
                ffma2(acc[3][j], z3, e2);
            }
        }

        // distances + running argmin (u64 key -> first-index tie-break)
        const int cbase = h * HCH + cg * 8;
        #pragma unroll
        for (int j = 0; j < 4; ++j) {
            float esq0 = __ldg(&d_esq[cbase + 2 * j]);
            float esq1 = __ldg(&d_esq[cbase + 2 * j + 1]);
            #pragma unroll
            for (int p = 0; p < 4; ++p) {
                float zq2 = zsq_s[pt_t * 4 + p];
                float2 dot = upk(acc[p][j]);
                {
                    float d = __fadd_rn(__fadd_rn(zq2, esq0), -2.0f * dot.x);
                    unsigned long long k64 =
                        ((unsigned long long)ordf(d) << 32) | (unsigned)(cbase + 2 * j);
                    if (k64 < best[p]) best[p] = k64;
                }
                {
                    float d = __fadd_rn(__fadd_rn(zq2, esq1), -2.0f * dot.y);
                    unsigned long long k64 =
                        ((unsigned long long)ordf(d) << 32) | (unsigned)(cbase + 2 * j + 1);
                    if (k64 < best[p]) best[p] = k64;
                }
            }
        }
    }

    // cross-thread argmin reduction per point (8 code-groups per point)
    __syncthreads();
    #pragma unroll
    for (int p = 0; p < 4; ++p) red[cg][pt_t * 4 + p] = best[p];
    __syncthreads();

    if (tid < PTSB) {
        unsigned long long bk = red[0][tid];
        #pragma unroll
        for (int t = 1; t < 8; ++t) {
            unsigned long long v = red[t][tid];
            if (v < bk) bk = v;
        }
        int idx = (int)(unsigned int)bk;
        int n   = pt0 + tid;

        out[OFF_IDX + n] = (float)idx;
        atomicAdd(&d_count[idx], 1u);
        out[OFF_ENC + (unsigned long long)n * NE + (unsigned)idx] = 1.0f;

        // z_q gather + loss partial (straight-through: z_q_out == z_q in value)
        float errsum = 0.f;
        const float* er = emb + (size_t)idx * DIM;
        float* zq = out + OFF_ZQ + (size_t)b * BHW + hw0 + tid;
        #pragma unroll
        for (int c = 0; c < DIM; ++c) {
            float e  = __ldg(er + c);
            float zv = zs[c][tid];
            float df = e - zv;
            errsum   = fmaf(df, df, errsum);
            zq[(size_t)c * HW] = e;
        }
        #pragma unroll
        for (int o = 16; o > 0; o >>= 1)
            errsum += __shfl_down_sync(0xFFFFFFFFu, errsum, o);
        if ((tid & 31) == 0) atomicAdd(&d_loss, errsum);
    }
}

// ---------------------------------------------------------------- finalize scalars
__global__ void finalize_kernel(float* __restrict__ out) {
    __shared__ float warp_s[32];
    int t = threadIdx.x;  // 1024 threads
    float em = (float)d_count[t] * (1.0f / 32768.0f);
    float v  = em * logf(em + 1e-10f);
    #pragma unroll
    for (int o = 16; o > 0; o >>= 1) v += __shfl_down_sync(0xFFFFFFFFu, v, o);
    if ((t & 31) == 0) warp_s[t >> 5] = v;
    __syncthreads();
    if (t < 32) {
        float w = warp_s[t];
        #pragma unroll
        for (int o = 16; o > 0; o >>= 1) w += __shfl_down_sync(0xFFFFFFFFu, w, o);
        if (t == 0) {
            out[OFF_PERP] = expf(-w);
            out[OFF_LOSS] = 1.25f * d_loss * (1.0f / 2097152.0f);
        }
    }
}

// ---------------------------------------------------------------- launch
extern "C" void kernel_launch(void* const* d_in, const int* in_sizes, int n_in,
                              void* d_out, int out_size) {
    const float* z   = (const float*)d_in[0];
    const float* emb = (const float*)d_in[1];
    float*       out = (float*)d_out;

    prep_kernel<<<16, 128>>>(emb);
    vq_main_kernel<<<NPTS / PTSB, 128>>>(z, emb, out);
    finalize_kernel<<<1, 1024>>>(out);
}